// round 10
// baseline (speedup 1.0000x reference)
#include <cuda_runtime.h>
#include <cuda_bf16.h>

// PlotLine2: histogram of rounded lerp points + separable 7-tap Gaussian conv.
// R7/R8: conv axes reordered so both passes are vector-load/vector-store;
// packed f32x2 FFMA (2 outputs/instr); T buffer needs no zeroing.
// Layout: C[iy_local][x+3] (stride 136), T[iy_local][s] (stride 128).
// (R8 = R7 resubmission: container infra failure, no kernel evidence.)

#define N_IMG    128
#define P_PTS    16
#define S_IMG    128
#define D_RAD    3
#define NTAP     7
#define C_ROWS   70                  // iy in [64h-3, 64h+66]
#define C_STRIDE 136                 // cols 0..133 used (x+3), padded, 16B-aligned rows
#define C_SIZE   (C_ROWS * C_STRIDE) // 9520
#define T_STRIDE 128
#define T_SIZE   (C_ROWS * T_STRIDE) // 8960
#define THREADS  512
#define NWARP    (THREADS / 32)

typedef unsigned long long u64t;

__device__ __forceinline__ u64t pack2(float lo, float hi) {
    u64t r;
    asm("mov.b64 %0, {%1, %2};" : "=l"(r) : "f"(lo), "f"(hi));
    return r;
}
__device__ __forceinline__ u64t mul2(u64t a, u64t b) {
    u64t r;
    asm("mul.rn.f32x2 %0, %1, %2;" : "=l"(r) : "l"(a), "l"(b));
    return r;
}
__device__ __forceinline__ u64t fma2(u64t a, u64t b, u64t c) {
    u64t r;
    asm("fma.rn.f32x2 %0, %1, %2, %3;" : "=l"(r) : "l"(a), "l"(b), "l"(c));
    return r;
}
__device__ __forceinline__ u64t add2(u64t a, u64t b) {
    u64t r;
    asm("add.rn.f32x2 %0, %1, %2;" : "=l"(r) : "l"(a), "l"(b));
    return r;
}
__device__ __forceinline__ void unpack2(u64t p, float& lo, float& hi) {
    asm("mov.b64 {%0, %1}, %2;" : "=f"(lo), "=f"(hi) : "l"(p));
}
__device__ __forceinline__ float tanh_approx(float x) {
    float r;
    asm("tanh.approx.f32 %0, %1;" : "=f"(r) : "f"(x));
    return r;
}

// 7-tap conv of pair-window P at offset i (matches scalar ((a0+a1)+a2) tree)
__device__ __forceinline__ u64t conv7(const u64t* P, const u64t* W2, int i) {
    u64t a0 = mul2(W2[0], P[i + 0]);
    u64t a1 = mul2(W2[1], P[i + 1]);
    u64t a2 = mul2(W2[2], P[i + 2]);
    a0 = fma2(W2[3], P[i + 3], a0);
    a1 = fma2(W2[4], P[i + 4], a1);
    a2 = fma2(W2[5], P[i + 5], a2);
    a0 = fma2(W2[6], P[i + 6], a0);
    return add2(add2(a0, a1), a2);
}

__global__ __launch_bounds__(THREADS, 2)
void plotline2_kernel(const float* __restrict__ points, float* __restrict__ out) {
    extern __shared__ float sm[];
    float* C   = sm;               // [C_ROWS][C_STRIDE] histogram (row = iy - (64h-3), col = ix+3)
    float* T   = sm + C_SIZE;      // [C_ROWS][T_STRIDE] x-convolved rows
    float* pts = T + T_SIZE;       // [2*P_PTS]

    const int tid  = threadIdx.x;
    const int n    = blockIdx.x >> 1;
    const int hf   = blockIdx.x & 1;     // output t range [64*hf, 64*hf+63]
    const int w    = tid >> 5;
    const int lane = tid & 31;

    // ---- Phase 0: zero C (vectorized); stage control points ----
    {
        float4* z = (float4*)C;
        const float4 z4 = make_float4(0.f, 0.f, 0.f, 0.f);
        for (int i = tid; i < C_SIZE / 4; i += THREADS) z[i] = z4;
    }
    if (tid < 2 * P_PTS) pts[tid] = points[n * (2 * P_PTS) + tid];
    __syncthreads();

    // ---- Phase 1: run-length-deduped histogram (filtered to this CTA's iy range) ----
    // Exact ref arithmetic: t=i/128 exact, non-contracted mul/mul/add, rintf (RNE).
    if (tid < 480) {
        const int rbase = 64 * hf - 3;
        int j0 = tid * 4;
        int lastAddr = -1;
        float cnt = 0.0f;
#pragma unroll
        for (int jj = 0; jj < 4; jj++) {
            int j   = j0 + jj;
            int seg = j >> 7;
            int i   = j & (S_IMG - 1);
            float t   = (float)i * (1.0f / (float)S_IMG);
            float omt = 1.0f - t;
            float x = __fadd_rn(__fmul_rn(omt, pts[seg * 2 + 0]), __fmul_rn(t, pts[seg * 2 + 2]));
            float y = __fadd_rn(__fmul_rn(omt, pts[seg * 2 + 1]), __fmul_rn(t, pts[seg * 2 + 3]));
            int ix = (int)rintf(x);            // 0..128
            int iy = (int)rintf(y);            // 0..128
            int row = iy - rbase;
            if ((unsigned)row < (unsigned)C_ROWS) {
                int addr = row * C_STRIDE + ix + D_RAD;
                if (addr == lastAddr) {
                    cnt += 1.0f;
                } else {
                    if (lastAddr >= 0) atomicAdd(&C[lastAddr], cnt);
                    lastAddr = addr;
                    cnt = 1.0f;
                }
            }
        }
        if (lastAddr >= 0) atomicAdd(&C[lastAddr], cnt);
    }
    __syncthreads();

    // Gaussian taps exp(-d^2), d=-3..3
    const float W[NTAP] = {
        1.2340980408667956e-4f, 1.8315638888734179e-2f, 0.36787944117144233f,
        1.0f,
        0.36787944117144233f,   1.8315638888734179e-2f, 1.2340980408667956e-4f
    };

    // ---- Phase 2: x-conv.  T[r][s] = sum_k W[k] * C[r][s+k]  (col = x+3 absorbed) ----
    // thread-task tt -> (row r, s-chunk c of 8); vector loads + packed FFMA + vector stores.
    {
        u64t W2[NTAP];
#pragma unroll
        for (int k = 0; k < NTAP; k++) W2[k] = pack2(W[k], W[k]);

        for (int tt = tid; tt < C_ROWS * 16; tt += THREADS) {
            int r  = tt >> 4;
            int s0 = (tt & 15) * 8;
            const float* base = &C[r * C_STRIDE + s0];
            float win[16];
#pragma unroll
            for (int q = 0; q < 4; q++) {
                float4 v = *(const float4*)(base + q * 4);
                win[q * 4 + 0] = v.x; win[q * 4 + 1] = v.y;
                win[q * 4 + 2] = v.z; win[q * 4 + 3] = v.w;
            }
            u64t P[13];
#pragma unroll
            for (int j = 0; j < 13; j++) P[j] = pack2(win[j], win[j + 1]);
            u64t r0 = conv7(P, W2, 0);
            u64t r1 = conv7(P, W2, 2);
            u64t r2 = conv7(P, W2, 4);
            u64t r3 = conv7(P, W2, 6);
            u64t* dst = (u64t*)&T[r * T_STRIDE + s0];
            *(ulonglong2*)(dst + 0) = make_ulonglong2(r0, r1);
            *(ulonglong2*)(dst + 2) = make_ulonglong2(r2, r3);
        }
    }
    __syncthreads();

    // ---- Phase 3: y-conv + tanh + coalesced vector store ----
    // out[s][64h+t0+i] = tanh( sum_k W[k] * T[t0+i+k][s] )
    // lane -> s (contiguous, conflict-free); 8 outputs contiguous in gmem.
    {
        u64t W2[NTAP];
#pragma unroll
        for (int k = 0; k < NTAP; k++) W2[k] = pack2(W[k], W[k]);

        float* o = out + n * (S_IMG * S_IMG) + 64 * hf;
        for (int task = w; task < 32; task += NWARP) {
            int sg = task >> 3;
            int tc = task & 7;
            int s  = sg * 32 + lane;
            int t0 = tc * 8;
            float win[14];
#pragma unroll
            for (int j = 0; j < 14; j++) win[j] = T[(t0 + j) * T_STRIDE + s];
            u64t P[13];
#pragma unroll
            for (int j = 0; j < 13; j++) P[j] = pack2(win[j], win[j + 1]);
            float res[8];
#pragma unroll
            for (int i = 0; i < 4; i++) {
                float lo, hi;
                unpack2(conv7(P, W2, 2 * i), lo, hi);
                res[2 * i + 0] = tanh_approx(lo);
                res[2 * i + 1] = tanh_approx(hi);
            }
            float4* dst = (float4*)&o[s * S_IMG + t0];
            dst[0] = make_float4(res[0], res[1], res[2], res[3]);
            dst[1] = make_float4(res[4], res[5], res[6], res[7]);
        }
    }
}

extern "C" void kernel_launch(void* const* d_in, const int* in_sizes, int n_in,
                              void* d_out, int out_size) {
    const float* points = (const float*)d_in[0];
    float* out = (float*)d_out;
    size_t smem = (size_t)(C_SIZE + T_SIZE + 2 * P_PTS) * sizeof(float);
    cudaFuncSetAttribute(plotline2_kernel,
                         cudaFuncAttributeMaxDynamicSharedMemorySize, (int)smem);
    plotline2_kernel<<<2 * N_IMG, THREADS, smem>>>(points, out);
}